// round 14
// baseline (speedup 1.0000x reference)
#include <cuda_runtime.h>
#include <math.h>

#define Bn 32
#define Rr 13
#define Cc 13
#define Aa 5
#define Kk 20
#define CELL 25
#define Nn 845                        // R*C*A
#define TOTAL (Bn * Nn)               // 27040
#define THRESH 0.5f
#define NMS_TH 0.4f

#define CPB 128                       // cells/block: 128*100B = 12800B, 16B-aligned
#define TPB 128
#define NBLK ((TOTAL + CPB - 1) / CPB)    // 212 (last block: 32 cells)
#define NBK (Bn * Kk)                 // 640
#define CAPS 64                       // candidate capacity per (b,k)
#define NMSBLK (NBK / TPB)            // 5 blocks, one thread per slot

// Static device scratch (no allocations allowed).
__device__ float                 g_cs[NBK * CAPS];
__device__ short                 g_cn[NBK * CAPS];
__device__ float4                g_cb[NBK * CAPS];
__device__ __align__(16) int     g_cnt[NBK];      // reset by NMS kernel each replay

__device__ __forceinline__ float sigmoid_(float v) {
    return 1.0f / (1.0f + __expf(-v));
}

// ---------------- Kernel A: decode + softmax + candidate compaction ----------
__global__ void __launch_bounds__(TPB)
region_decode(const float* __restrict__ x,
              const float* __restrict__ bias,
              float* __restrict__ out) {
    const int tid = threadIdx.x;
    const int blockBase = blockIdx.x * CPB;
    const int cells = min(CPB, TOTAL - blockBase);   // 128 or 32
    const int n4 = cells * CELL / 4;                 // 800 or 200

    __shared__ float s_data[CPB * CELL];             // 12.8 KB

    // Hoist per-cell index math + bias loads (overlap with staging loads).
    const int  gid   = blockBase + tid;
    const bool valid = (tid < cells);
    int n = 0, col = 0, row = 0, b2 = 0;
    float wb = 0.0f, hb = 0.0f;
    if (valid) {
        n  = gid % Nn;
        b2 = gid / Nn;
        int a    = n % Aa;
        int cell = n / Aa;
        col = cell % Cc;
        row = cell / Cc;
        wb = __ldg(&bias[2 * a]);
        hb = __ldg(&bias[2 * a + 1]);
    }

    // Coalesced float4 staging load.
    {
        const float4* src = (const float4*)(x + (size_t)blockBase * CELL);
        float4* dst = (float4*)s_data;
        for (int i = tid; i < n4; i += TPB) dst[i] = src[i];
    }
    __syncthreads();

    // Decode + inline softmax, in place in shared.
    if (valid) {
        float* t = s_data + tid * CELL;              // stride 25: conflict-free

        float bx  = (sigmoid_(t[0]) + (float)col) * (1.0f / (float)Cc);
        float by  = (sigmoid_(t[1]) + (float)row) * (1.0f / (float)Rr);
        float bw  = __expf(t[2]) * wb * (1.0f / (float)Rr);
        float bh  = __expf(t[3]) * hb * (1.0f / (float)Cc);
        float obj = sigmoid_(t[4]);

        t[0] = bx; t[1] = by; t[2] = bw; t[3] = bh; t[4] = obj;

        if (obj > THRESH) {
            float e[Kk];
            float s = 0.0f;
            #pragma unroll
            for (int j = 0; j < Kk; j++) { e[j] = __expf(t[5 + j]); s += e[j]; }
            float inv = 1.0f / s;

            float x1 = bx - 0.5f * bw;
            float y1 = by - 0.5f * bh;
            float4 box = make_float4(x1, y1, x1 + bw, y1 + bh);

            #pragma unroll
            for (int j = 0; j < Kk; j++) {
                float p = obj * e[j] * inv;
                if (p > THRESH) {
                    t[5 + j] = p;
                    int slot = b2 * Kk + j;
                    int q = atomicAdd(&g_cnt[slot], 1);
                    if (q < CAPS) {
                        g_cs[slot * CAPS + q] = p;
                        g_cn[slot * CAPS + q] = (short)n;
                        g_cb[slot * CAPS + q] = box;
                    }
                } else {
                    t[5 + j] = 0.0f;
                }
            }
        } else {
            #pragma unroll
            for (int j = 0; j < Kk; j++) t[5 + j] = 0.0f;
        }
    }
    __syncthreads();

    // Coalesced float4 store.
    {
        const float4* src = (const float4*)s_data;
        float4* dst = (float4*)(out + (size_t)blockBase * CELL);
        for (int i = tid; i < n4; i += TPB) dst[i] = src[i];
    }
}

// ---------------- Kernel B: one thread per (b,k) slot ------------------------
__global__ void __launch_bounds__(TPB)
region_nms(float* __restrict__ out) {
    const int slot = blockIdx.x * TPB + threadIdx.x;   // 0..639, coalesced

    int V = g_cnt[slot];
    if (V == 0) return;                // already zero, no reset store needed
    g_cnt[slot] = 0;                   // reset for next graph replay
    if (V == 1) return;
    if (V > CAPS) V = CAPS;

    const int b = slot / Kk;
    const int k = slot % Kk;
    const float*  cs = g_cs + (size_t)slot * CAPS;
    const short*  cn = g_cn + (size_t)slot * CAPS;
    const float4* cb = g_cb + (size_t)slot * CAPS;

    unsigned sup[2] = {0u, 0u}, used[2] = {0u, 0u};

    // Greedy in (score desc, index asc) order — matches stable argsort.
    for (int it = 0; it < V; it++) {
        int   best = -1, bi = 0x7fffffff;
        float bs = -1.0f;
        for (int j = 0; j < V; j++) {
            if ((used[j >> 5] >> (j & 31)) & 1u) continue;
            float sj = cs[j];
            int   nj = cn[j];
            if (sj > bs || (sj == bs && nj < bi)) { best = j; bs = sj; bi = nj; }
        }
        used[best >> 5] |= 1u << (best & 31);
        if ((sup[best >> 5] >> (best & 31)) & 1u) continue;   // not alive

        float4 bb = cb[best];
        float  ab = (bb.z - bb.x) * (bb.w - bb.y);
        for (int j = 0; j < V; j++) {
            if ((used[j >> 5] >> (j & 31)) & 1u) continue;
            if ((sup[j >> 5]  >> (j & 31)) & 1u) continue;
            float4 cj = cb[j];
            float iw = fminf(bb.z, cj.z) - fmaxf(bb.x, cj.x);
            float ih = fminf(bb.w, cj.w) - fmaxf(bb.y, cj.y);
            iw = fmaxf(iw, 0.0f);
            ih = fmaxf(ih, 0.0f);
            float inter = iw * ih;
            float aj    = (cj.z - cj.x) * (cj.w - cj.y);
            float uni   = fmaxf(ab + aj - inter, 1e-9f);
            if (inter / uni > NMS_TH) sup[j >> 5] |= 1u << (j & 31);
        }
    }
    for (int j = 0; j < V; j++) {
        if ((sup[j >> 5] >> (j & 31)) & 1u)
            out[((size_t)(b * Nn + cn[j])) * CELL + 5 + k] = 0.0f;
    }
}

extern "C" void kernel_launch(void* const* d_in, const int* in_sizes, int n_in,
                              void* d_out, int out_size) {
    const float* x    = (const float*)d_in[0];
    const float* bias = (const float*)d_in[1];
    float* out        = (float*)d_out;
    region_decode<<<NBLK, TPB>>>(x, bias, out);
    region_nms<<<NMSBLK, TPB>>>(out);
}